// round 3
// baseline (speedup 1.0000x reference)
#include <cuda_runtime.h>

// dwtHaar_2d: x (8,64,512,512) f32 -> 4 subbands (8,64,256,256) concatenated.
// Reflect pad left/top by 1, stride 2, kernel 2 => non-overlapping windows.
// out[s][bc][i][j], s in {LL, LH, HL, HH}.
//
// R2: 4 output cols / thread (4x LDG.128 in, 4x STG.128 out), 2 output rows
// per 128-thread block, streaming stores.

namespace {
constexpr int H  = 512;
constexpr int W  = 512;
constexpr int Ho = 256;
constexpr int Wo = 256;
constexpr int BC = 8 * 64;                         // 512
constexpr long long SUB = (long long)BC * Ho * Wo; // elements per subband
}

__global__ __launch_bounds__(128) void dwt_haar_kernel(
    const float* __restrict__ x, float* __restrict__ out)
{
    const int t    = threadIdx.x;          // 0..127
    const int half = t >> 6;               // which of the 2 output rows
    const int u    = t & 63;               // 0..63: handles output cols [4u, 4u+4)
    const int i    = blockIdx.x * 2 + half;  // output row 0..255
    const int bc   = blockIdx.y;             // 0..511

    const float* base  = x + (size_t)bc * (H * W);
    const int    r_top = (i == 0) ? 1 : (2 * i - 1);  // reflect row -1 -> row 1
    const int    r_bot = 2 * i;

    const float* rowt = base + (size_t)r_top * W;
    const float* rowb = base + (size_t)r_bot * W;

    // 4 independent aligned 16B loads: input cols [8u, 8u+8) of both rows.
    const float4 t0 = reinterpret_cast<const float4*>(rowt)[2 * u];
    const float4 t1 = reinterpret_cast<const float4*>(rowt)[2 * u + 1];
    const float4 b0 = reinterpret_cast<const float4*>(rowb)[2 * u];
    const float4 b1 = reinterpret_cast<const float4*>(rowb)[2 * u + 1];

    // Left neighbor element (input col 8u-1) = previous thread's t1.w / b1.w.
    float lt = __shfl_up_sync(0xffffffffu, t1.w, 1);
    float lb = __shfl_up_sync(0xffffffffu, b1.w, 1);
    if ((t & 31) == 0) {
        if (u == 0) {            // col -1 reflects to col 1
            lt = t0.y;
            lb = b0.y;
        } else {                 // cross-warp lane: one scalar load (L1/L2 hit)
            lt = rowt[8 * u - 1];
            lb = rowb[8 * u - 1];
        }
    }

    // e[-1..6] per row: windows for output cols 4u+p use (e[2p-1], e[2p]).
    const float et[8] = {lt, t0.x, t0.y, t0.z, t0.w, t1.x, t1.y, t1.z};
    const float eb[8] = {lb, b0.x, b0.y, b0.z, b0.w, b1.x, b1.y, b1.z};

    float4 ll, lh, hl, hh;
    float* pll = &ll.x; float* plh = &lh.x; float* phl = &hl.x; float* phh = &hh.x;
    #pragma unroll
    for (int p = 0; p < 4; p++) {
        const float a = et[2 * p];     // col 8u+2p-1, top
        const float b = et[2 * p + 1]; // col 8u+2p,   top
        const float c = eb[2 * p];     // bottom
        const float d = eb[2 * p + 1];
        pll[p] = 0.5f * ( a + b + c + d);
        plh[p] = 0.5f * ( a + b - c - d);
        phl[p] = 0.5f * (-a + b - c + d);
        phh[p] = 0.5f * ( a - b - c + d);
    }

    const size_t obase = (size_t)bc * (Ho * Wo) + (size_t)i * Wo + 4 * u;
    __stcs(reinterpret_cast<float4*>(out + obase),           ll);
    __stcs(reinterpret_cast<float4*>(out + SUB + obase),     lh);
    __stcs(reinterpret_cast<float4*>(out + 2 * SUB + obase), hl);
    __stcs(reinterpret_cast<float4*>(out + 3 * SUB + obase), hh);
}

extern "C" void kernel_launch(void* const* d_in, const int* in_sizes, int n_in,
                              void* d_out, int out_size)
{
    const float* x = (const float*)d_in[0];
    float* out     = (float*)d_out;

    dim3 grid(Ho / 2, BC);   // (128, 512)
    dim3 block(128);
    dwt_haar_kernel<<<grid, block>>>(x, out);
}